// round 3
// baseline (speedup 1.0000x reference)
#include <cuda_runtime.h>

// Problem shape (fixed by the dataset): input (B,H,W,C) = (16,128,128,128) fp32,
// FACTOR=(2,2) half-pixel bilinear upsample -> output (16,256,256,128) fp32.
//
// Half-pixel mapping for factor 2: out index o -> src coord o*0.5 - 0.25.
//   i0 = floor(src) = (o-1)>>1 (arith shift handles o=0 -> -1)
//   frac = 0.75 if o even, 0.25 if o odd
//   lo = clamp(i0, 0, n-1), hi = clamp(i0+1, 0, n-1); frac = 0 when hi==lo.
// This matches the reference's _axis_interp exactly.

#define B_ 16
#define H_ 128
#define W_ 128
#define C4_ 32           // 128 channels / 4 (float4)
#define OH_ 256
#define OW_ 256

__global__ __launch_bounds__(256) void upsample2x_kernel(
    const float4* __restrict__ in, float4* __restrict__ out, int total4)
{
    int idx = blockIdx.x * blockDim.x + threadIdx.x;
    if (idx >= total4) return;

    int c4 = idx & (C4_ - 1);
    int ow = (idx >> 5) & (OW_ - 1);
    int oh = (idx >> 13) & (OH_ - 1);
    int b  = idx >> 21;

    // H axis taps/weight
    int ih0 = (oh - 1) >> 1;
    int hlo = ih0 < 0 ? 0 : ih0;
    int hhi = ih0 + 1 > H_ - 1 ? H_ - 1 : ih0 + 1;
    float th = (hhi > hlo) ? ((oh & 1) ? 0.25f : 0.75f) : 0.0f;

    // W axis taps/weight
    int iw0 = (ow - 1) >> 1;
    int wlo = iw0 < 0 ? 0 : iw0;
    int whi = iw0 + 1 > W_ - 1 ? W_ - 1 : iw0 + 1;
    float tw = (whi > wlo) ? ((ow & 1) ? 0.25f : 0.75f) : 0.0f;

    const float4* rlo = in + ((size_t)(b * H_ + hlo) * W_) * C4_;
    const float4* rhi = in + ((size_t)(b * H_ + hhi) * W_) * C4_;

    float4 v00 = __ldg(&rlo[wlo * C4_ + c4]);
    float4 v01 = __ldg(&rlo[whi * C4_ + c4]);
    float4 v10 = __ldg(&rhi[wlo * C4_ + c4]);
    float4 v11 = __ldg(&rhi[whi * C4_ + c4]);

    // H interp first, then W (matches reference order).
    float4 a, bb, r;
    a.x = fmaf(th, v10.x - v00.x, v00.x);
    a.y = fmaf(th, v10.y - v00.y, v00.y);
    a.z = fmaf(th, v10.z - v00.z, v00.z);
    a.w = fmaf(th, v10.w - v00.w, v00.w);
    bb.x = fmaf(th, v11.x - v01.x, v01.x);
    bb.y = fmaf(th, v11.y - v01.y, v01.y);
    bb.z = fmaf(th, v11.z - v01.z, v01.z);
    bb.w = fmaf(th, v11.w - v01.w, v01.w);
    r.x = fmaf(tw, bb.x - a.x, a.x);
    r.y = fmaf(tw, bb.y - a.y, a.y);
    r.z = fmaf(tw, bb.z - a.z, a.z);
    r.w = fmaf(tw, bb.w - a.w, a.w);

    // Streaming store: output is never re-read; keep L2 for the input reuse window.
    __stcs(&out[idx], r);
}

extern "C" void kernel_launch(void* const* d_in, const int* in_sizes, int n_in,
                              void* d_out, int out_size) {
    const float4* in = (const float4*)d_in[0];
    float4* out = (float4*)d_out;
    int total4 = out_size / 4;  // 33,554,432 float4s
    int threads = 256;
    int blocks = (total4 + threads - 1) / threads;
    upsample2x_kernel<<<blocks, threads>>>(in, out, total4);
}

// round 4
// speedup vs baseline: 1.4441x; 1.4441x over previous
#include <cuda_runtime.h>

// Input (B,H,W,C) = (16,128,128,128) fp32, factor (2,2) half-pixel bilinear
// upsample -> (16,256,256,128) fp32.
//
// Quad formulation: for interior outputs, rows 2q+1 and 2q+2 both use source
// rows (q, q+1) with fracs 0.25 and 0.75 (same for columns). One thread per
// (b, qh, qw, c4): 4 float4 tap loads -> 4 float4 stores. Output row/col 0
// (frac collapses to a copy of source row/col 0) is emitted by the qh==0 /
// qw==0 threads as extra predicated stores; row/col 255 come from q=127 with
// clamped identical taps (v1==v0 -> exact copy via fma form).

#define B_   16
#define H_   128
#define W_   128
#define C4_  32          // 128 channels / 4
#define OH_  256
#define OW_  256

__device__ __forceinline__ float4 lerp4(float4 v0, float4 v1, float t) {
    float4 r;
    r.x = fmaf(t, v1.x - v0.x, v0.x);
    r.y = fmaf(t, v1.y - v0.y, v0.y);
    r.z = fmaf(t, v1.z - v0.z, v0.z);
    r.w = fmaf(t, v1.w - v0.w, v0.w);
    return r;
}

__global__ __launch_bounds__(256) void upsample2x_quad(
    const float4* __restrict__ in, float4* __restrict__ out)
{
    int idx = blockIdx.x * 256 + threadIdx.x;   // exactly B*128*128*32 threads
    int c4 = idx & (C4_ - 1);
    int qw = (idx >> 5) & (W_ - 1);
    int qh = (idx >> 12) & (H_ - 1);
    int b  = idx >> 19;

    int r1 = qh < H_ - 1 ? qh + 1 : H_ - 1;
    int c1 = qw < W_ - 1 ? qw + 1 : W_ - 1;

    const float4* base = in + (size_t)b * (H_ * W_ * C4_) + c4;
    float4 v00 = __ldg(base + (qh * W_ + qw) * C4_);
    float4 v01 = __ldg(base + (qh * W_ + c1) * C4_);
    float4 v10 = __ldg(base + (r1 * W_ + qw) * C4_);
    float4 v11 = __ldg(base + (r1 * W_ + c1) * C4_);

    // H interpolation (matches reference: H first, then W).
    float4 a0 = lerp4(v00, v10, 0.25f);   // output row 2qh+1, col taps at qw
    float4 a1 = lerp4(v01, v11, 0.25f);   //                   col taps at c1
    float4 b0 = lerp4(v00, v10, 0.75f);   // output row 2qh+2
    float4 b1 = lerp4(v01, v11, 0.75f);

    float4* obase = out + (size_t)b * (OH_ * OW_ * C4_) + c4;
    int rowA = 2 * qh + 1;
    int colA = 2 * qw + 1;

    // Interior 2x2 quad
    __stcs(obase + (rowA * OW_ + colA) * C4_, lerp4(a0, a1, 0.25f));
    if (qw < W_ - 1)
        __stcs(obase + (rowA * OW_ + colA + 1) * C4_, lerp4(a0, a1, 0.75f));
    if (qh < H_ - 1) {
        int rowB = rowA + 1;
        __stcs(obase + (rowB * OW_ + colA) * C4_, lerp4(b0, b1, 0.25f));
        if (qw < W_ - 1)
            __stcs(obase + (rowB * OW_ + colA + 1) * C4_, lerp4(b0, b1, 0.75f));
    }

    // Output row 0 = source row 0 (h-frac collapses), w-interp as usual.
    if (qh == 0) {
        __stcs(obase + colA * C4_, lerp4(v00, v01, 0.25f));
        if (qw < W_ - 1)
            __stcs(obase + (colA + 1) * C4_, lerp4(v00, v01, 0.75f));
        if (qw == 0)
            __stcs(obase, v00);                    // (0,0) corner
    }

    // Output col 0 = source col 0 (w-frac collapses), h-interp values a0/b0.
    if (qw == 0) {
        __stcs(obase + (rowA * OW_) * C4_, a0);
        if (qh < H_ - 1)
            __stcs(obase + ((rowA + 1) * OW_) * C4_, b0);
    }
}

extern "C" void kernel_launch(void* const* d_in, const int* in_sizes, int n_in,
                              void* d_out, int out_size) {
    const float4* in = (const float4*)d_in[0];
    float4* out = (float4*)d_out;
    int total = B_ * H_ * W_ * C4_;        // 8,388,608 threads
    upsample2x_quad<<<total / 256, 256>>>(in, out);
}